// round 1
// baseline (speedup 1.0000x reference)
#include <cuda_runtime.h>
#include <math.h>

// ---------------- problem constants ----------------
#define Lnum 4
#define Bn   2
#define Sn   1024
#define En   1024
#define NHn  16
#define HDn  64
#define HIDn 1024
#define FFn  4096
#define Vn   32000
#define NTOK (Bn*Sn)   // 2048

// ---------------- scratch (static device memory; no allocation) ----------------
__device__ float g_x   [NTOK*En];
__device__ float g_q   [NTOK*HIDn];
__device__ float g_k   [NTOK*HIDn];
__device__ float g_v   [NTOK*HIDn];
__device__ float g_att [(size_t)Bn*NHn*Sn*Sn];   // 128 MB
__device__ float g_mha [NTOK*HIDn];
__device__ float g_proj[NTOK*En];
__device__ float g_rn  [NTOK*En];
__device__ float g_ffh [NTOK*FFn];               // 32 MB

// ---------------- block reductions ----------------
__device__ __forceinline__ float blockReduceSum(float v) {
    __shared__ float sh[33];
    int lane = threadIdx.x & 31, w = threadIdx.x >> 5;
    #pragma unroll
    for (int o = 16; o > 0; o >>= 1) v += __shfl_xor_sync(0xffffffffu, v, o);
    __syncthreads();
    if (lane == 0) sh[w] = v;
    __syncthreads();
    if (w == 0) {
        v = (lane < (int)(blockDim.x >> 5)) ? sh[lane] : 0.f;
        #pragma unroll
        for (int o = 16; o > 0; o >>= 1) v += __shfl_xor_sync(0xffffffffu, v, o);
        if (lane == 0) sh[32] = v;
    }
    __syncthreads();
    return sh[32];
}

__device__ __forceinline__ float blockReduceMax(float v) {
    __shared__ float sh[33];
    int lane = threadIdx.x & 31, w = threadIdx.x >> 5;
    #pragma unroll
    for (int o = 16; o > 0; o >>= 1) v = fmaxf(v, __shfl_xor_sync(0xffffffffu, v, o));
    __syncthreads();
    if (lane == 0) sh[w] = v;
    __syncthreads();
    if (w == 0) {
        v = (lane < (int)(blockDim.x >> 5)) ? sh[lane] : -3.402823466e38f;
        #pragma unroll
        for (int o = 16; o > 0; o >>= 1) v = fmaxf(v, __shfl_xor_sync(0xffffffffu, v, o));
        if (lane == 0) sh[32] = v;
    }
    __syncthreads();
    return sh[32];
}

// ---------------- embedding: x = tok_embed[tokens] + pos_embed[s] ----------------
__global__ void embed_kernel(const int* __restrict__ tokens,
                             const float* __restrict__ tok,
                             const float* __restrict__ pos,
                             float* __restrict__ x) {
    int idx = blockIdx.x * blockDim.x + threadIdx.x;
    const int EV = En / 4;
    if (idx >= NTOK * EV) return;
    int bs = idx / EV, e4 = idx % EV;
    int s = bs & (Sn - 1);
    int t = tokens[bs];
    float4 a = ((const float4*)tok)[(size_t)t * EV + e4];
    float4 p = ((const float4*)pos)[(size_t)s * EV + e4];
    float4 r;
    r.x = a.x + p.x; r.y = a.y + p.y; r.z = a.z + p.z; r.w = a.w + p.w;
    ((float4*)x)[idx] = r;
}

// ---------------- generic SGEMM: C = A(MxK) * B(KxN), row-major ----------------
// flags: 1 = +bias[N], 2 = relu, 4 = +add (residual, MxN)
template<int BM>
__global__ void __launch_bounds__(256) gemm_nn(
    const float* __restrict__ A, const float* __restrict__ Bm,
    const float* __restrict__ bias, const float* __restrict__ add,
    float* __restrict__ C, int M, int N, int K, int flags)
{
    constexpr int BN = 128, BK = 16;
    constexpr int TM = (BM == 128) ? 8 : 4;
    __shared__ float As[BK][BM + 4];
    __shared__ float Bs[BK][BN];
    const int tid = threadIdx.x;
    const int tx = tid & 15, ty = tid >> 4;
    const float* Ab = A  + (size_t)blockIdx.y * BM * K;
    const float* Bb = Bm + (size_t)blockIdx.x * BN;
    float acc[TM][8];
    #pragma unroll
    for (int i = 0; i < TM; i++)
        #pragma unroll
        for (int j = 0; j < 8; j++) acc[i][j] = 0.f;

    const int a_r = tid >> 2, a_c = (tid & 3) << 2;
    const int b_r = tid >> 5, b_c = (tid & 31) << 2;

    for (int k0 = 0; k0 < K; k0 += BK) {
        #pragma unroll
        for (int p = 0; p < BM / 64; p++) {
            int r = a_r + p * 64;
            float4 va = *(const float4*)(Ab + (size_t)r * K + k0 + a_c);
            As[a_c + 0][r] = va.x; As[a_c + 1][r] = va.y;
            As[a_c + 2][r] = va.z; As[a_c + 3][r] = va.w;
        }
        #pragma unroll
        for (int p = 0; p < 2; p++) {
            int r = b_r + p * 8;
            *(float4*)&Bs[r][b_c] = *(const float4*)(Bb + (size_t)(k0 + r) * N + b_c);
        }
        __syncthreads();
        #pragma unroll
        for (int k = 0; k < BK; k++) {
            float ra[TM], rb[8];
            *(float4*)&ra[0] = *(const float4*)&As[k][ty * 4];
            if constexpr (TM == 8) {
                *(float4*)&ra[4] = *(const float4*)&As[k][64 + ty * 4];
            }
            *(float4*)&rb[0] = *(const float4*)&Bs[k][tx * 4];
            *(float4*)&rb[4] = *(const float4*)&Bs[k][64 + tx * 4];
            #pragma unroll
            for (int i = 0; i < TM; i++)
                #pragma unroll
                for (int j = 0; j < 8; j++)
                    acc[i][j] = fmaf(ra[i], rb[j], acc[i][j]);
        }
        __syncthreads();
    }

    #pragma unroll
    for (int i = 0; i < TM; i++) {
        int row = blockIdx.y * BM + ((i < 4) ? (ty * 4 + i) : (64 + ty * 4 + i - 4));
        float* Cr = C + (size_t)row * N + blockIdx.x * BN;
        const float* Ar = (flags & 4) ? (add + (size_t)row * N + blockIdx.x * BN) : nullptr;
        #pragma unroll
        for (int h = 0; h < 2; h++) {
            int col = h * 64 + tx * 4;
            float4 v;
            float* vp = (float*)&v;
            #pragma unroll
            for (int j = 0; j < 4; j++) {
                float t = acc[i][h * 4 + j];
                if (flags & 1) t += bias[blockIdx.x * BN + col + j];
                if (flags & 4) t += Ar[col + j];
                if (flags & 2) t = fmaxf(t, 0.f);
                vp[j] = t;
            }
            *(float4*)(Cr + col) = v;
        }
    }
}

// ---------------- scores[bh][s][t] = 0.125 * sum_d q[b,s,h,d]*k[b,t,h,d] ----------------
__global__ void __launch_bounds__(256) attn_scores_kernel(
    const float* __restrict__ q, const float* __restrict__ k, float* __restrict__ sc)
{
    const int bh = blockIdx.z, b = bh >> 4, h = bh & 15;
    const int s0 = blockIdx.y << 6, t0 = blockIdx.x << 6;
    __shared__ float Qs[64][68];
    __shared__ float Ks[64][68];
    const int tid = threadIdx.x, tx = tid & 15, ty = tid >> 4;
    const int lc = (tid & 15) << 2;
    const float* qb = q + (size_t)b * Sn * HIDn + h * HDn;
    const float* kb = k + (size_t)b * Sn * HIDn + h * HDn;
    #pragma unroll
    for (int p = 0; p < 4; p++) {
        int r = ty + (p << 4);
        *(float4*)&Qs[r][lc] = *(const float4*)(qb + (size_t)(s0 + r) * HIDn + lc);
        *(float4*)&Ks[r][lc] = *(const float4*)(kb + (size_t)(t0 + r) * HIDn + lc);
    }
    __syncthreads();
    float acc[4][4] = {};
    #pragma unroll
    for (int d = 0; d < 64; d += 4) {
        float4 av[4], bv[4];
        #pragma unroll
        for (int i = 0; i < 4; i++) av[i] = *(const float4*)&Qs[ty + (i << 4)][d];
        #pragma unroll
        for (int j = 0; j < 4; j++) bv[j] = *(const float4*)&Ks[tx + (j << 4)][d];
        #pragma unroll
        for (int i = 0; i < 4; i++)
            #pragma unroll
            for (int j = 0; j < 4; j++)
                acc[i][j] += av[i].x * bv[j].x + av[i].y * bv[j].y
                           + av[i].z * bv[j].z + av[i].w * bv[j].w;
    }
    const float scale = 0.125f;  // 1/sqrt(64)
    float* ob = sc + ((size_t)bh * Sn + s0) * Sn + t0;
    #pragma unroll
    for (int i = 0; i < 4; i++)
        #pragma unroll
        for (int j = 0; j < 4; j++)
            ob[(size_t)(ty + (i << 4)) * Sn + tx + (j << 4)] = acc[i][j] * scale;
}

// ---------------- softmax over last dim (UNMASKED — bug-faithful) ----------------
__global__ void softmax1024_kernel(float* __restrict__ a) {
    float* row = a + (size_t)blockIdx.x * Sn;
    int tid = threadIdx.x;
    float v[4];
    #pragma unroll
    for (int j = 0; j < 4; j++) v[j] = row[tid + j * 256];
    float m = fmaxf(fmaxf(v[0], v[1]), fmaxf(v[2], v[3]));
    m = blockReduceMax(m);
    float s = 0.f;
    #pragma unroll
    for (int j = 0; j < 4; j++) { v[j] = expf(v[j] - m); s += v[j]; }
    s = blockReduceSum(s);
    float inv = 1.f / s;
    #pragma unroll
    for (int j = 0; j < 4; j++) row[tid + j * 256] = v[j] * inv;
}

// ---------------- mha[b,t,h,d] = sum_s v[b,s,h,d]*attn[b,h,s,t] ----------------
__global__ void __launch_bounds__(256) attn_av_kernel(
    const float* __restrict__ attn, const float* __restrict__ v, float* __restrict__ mha)
{
    const int bh = blockIdx.z, b = bh >> 4, h = bh & 15;
    const int t0 = blockIdx.x << 6;
    __shared__ float As[64][68];  // [s][t]
    __shared__ float Vs[64][68];  // [s][d]
    const int tid = threadIdx.x, tx = tid & 15, ty = tid >> 4;
    const int lc = (tid & 15) << 2;
    const float* ab = attn + (size_t)bh * Sn * Sn;
    const float* vb = v + (size_t)b * Sn * HIDn + h * HDn;
    float acc[4][4] = {};
    for (int c0 = 0; c0 < Sn; c0 += 64) {
        #pragma unroll
        for (int p = 0; p < 4; p++) {
            int r = ty + (p << 4);
            *(float4*)&As[r][lc] = *(const float4*)(ab + (size_t)(c0 + r) * Sn + t0 + lc);
            *(float4*)&Vs[r][lc] = *(const float4*)(vb + (size_t)(c0 + r) * HIDn + lc);
        }
        __syncthreads();
        #pragma unroll
        for (int s = 0; s < 64; s++) {
            float a[4];
            #pragma unroll
            for (int i = 0; i < 4; i++) a[i] = As[s][ty + (i << 4)];
            float4 bv = *(const float4*)&Vs[s][tx << 2];
            #pragma unroll
            for (int i = 0; i < 4; i++) {
                acc[i][0] = fmaf(a[i], bv.x, acc[i][0]);
                acc[i][1] = fmaf(a[i], bv.y, acc[i][1]);
                acc[i][2] = fmaf(a[i], bv.z, acc[i][2]);
                acc[i][3] = fmaf(a[i], bv.w, acc[i][3]);
            }
        }
        __syncthreads();
    }
    float* ob = mha + (size_t)b * Sn * HIDn + h * HDn;
    #pragma unroll
    for (int i = 0; i < 4; i++) {
        float4 w;
        w.x = acc[i][0]; w.y = acc[i][1]; w.z = acc[i][2]; w.w = acc[i][3];
        *(float4*)(ob + (size_t)(t0 + ty + (i << 4)) * HIDn + (tx << 2)) = w;
    }
}

// ---------------- rn = rmsnorm(x [+ add]) * scale ----------------
__global__ void add_rmsnorm_kernel(const float* __restrict__ x, const float* __restrict__ add,
                                   const float* __restrict__ scale, float* __restrict__ out)
{
    int row = blockIdx.x, tid = threadIdx.x;
    const float* xr = x + (size_t)row * En;
    const float* ar = add ? add + (size_t)row * En : nullptr;
    float v[4]; float ss = 0.f;
    #pragma unroll
    for (int j = 0; j < 4; j++) {
        int e = tid + j * 256;
        float t = xr[e];
        if (ar) t += ar[e];
        v[j] = t;
        ss += t * t;
    }
    ss = blockReduceSum(ss);
    float r = rsqrtf(ss * (1.f / En) + 1e-6f);
    float* orow = out + (size_t)row * En;
    #pragma unroll
    for (int j = 0; j < 4; j++) {
        int e = tid + j * 256;
        orow[e] = v[j] * r * scale[e];
    }
}

// ---------------- in-place log_softmax over V=32000 ----------------
__global__ void log_softmax_kernel(float* __restrict__ a) {
    float* row = a + (size_t)blockIdx.x * Vn;
    int tid = threadIdx.x;
    float m = -3.402823466e38f;
    for (int i = tid; i < Vn; i += 256) m = fmaxf(m, row[i]);
    m = blockReduceMax(m);
    float s = 0.f;
    for (int i = tid; i < Vn; i += 256) s += expf(row[i] - m);
    s = blockReduceSum(s);
    float lse = m + logf(s);
    for (int i = tid; i < Vn; i += 256) row[i] -= lse;
}

// ---------------- launch ----------------
extern "C" void kernel_launch(void* const* d_in, const int* in_sizes, int n_in,
                              void* d_out, int out_size) {
    const int*   tokens      = (const int*)  d_in[0];
    const float* tok_embed   = (const float*)d_in[1];
    const float* pos_embed   = (const float*)d_in[2];
    const float* Qw          = (const float*)d_in[3];
    const float* Kw          = (const float*)d_in[4];
    const float* Vw          = (const float*)d_in[5];
    const float* Ow          = (const float*)d_in[6];
    const float* rs2         = (const float*)d_in[7];
    const float* w1          = (const float*)d_in[8];
    const float* b1          = (const float*)d_in[9];
    const float* w2          = (const float*)d_in[10];
    const float* b2          = (const float*)d_in[11];
    const float* final_scale = (const float*)d_in[12];
    const float* w_out       = (const float*)d_in[13];
    const float* b_out       = (const float*)d_in[14];
    float* out = (float*)d_out;

    float *xb, *qb, *kb, *vb, *attb, *mhab, *projb, *rnb, *hb;
    cudaGetSymbolAddress((void**)&xb,    g_x);
    cudaGetSymbolAddress((void**)&qb,    g_q);
    cudaGetSymbolAddress((void**)&kb,    g_k);
    cudaGetSymbolAddress((void**)&vb,    g_v);
    cudaGetSymbolAddress((void**)&attb,  g_att);
    cudaGetSymbolAddress((void**)&mhab,  g_mha);
    cudaGetSymbolAddress((void**)&projb, g_proj);
    cudaGetSymbolAddress((void**)&rnb,   g_rn);
    cudaGetSymbolAddress((void**)&hb,    g_ffh);

    embed_kernel<<<(NTOK * (En / 4) + 255) / 256, 256>>>(tokens, tok_embed, pos_embed, xb);

    for (int l = 0; l < Lnum; l++) {
        const float* Ql  = Qw + (size_t)l * En * HIDn;
        const float* Kl  = Kw + (size_t)l * En * HIDn;
        const float* Vl  = Vw + (size_t)l * En * HIDn;
        const float* Ol  = Ow + (size_t)l * HIDn * En;
        const float* r2l = rs2 + (size_t)l * En;
        const float* w1l = w1 + (size_t)l * En * FFn;
        const float* b1l = b1 + (size_t)l * FFn;
        const float* w2l = w2 + (size_t)l * FFn * En;
        const float* b2l = b2 + (size_t)l * En;

        dim3 gN1024(HIDn / 128, NTOK / 64);
        gemm_nn<64><<<gN1024, 256>>>(xb, Ql, nullptr, nullptr, qb, NTOK, HIDn, En, 0);
        gemm_nn<64><<<gN1024, 256>>>(xb, Kl, nullptr, nullptr, kb, NTOK, HIDn, En, 0);
        gemm_nn<64><<<gN1024, 256>>>(xb, Vl, nullptr, nullptr, vb, NTOK, HIDn, En, 0);

        attn_scores_kernel<<<dim3(Sn / 64, Sn / 64, Bn * NHn), 256>>>(qb, kb, attb);
        softmax1024_kernel<<<Bn * NHn * Sn, 256>>>(attb);
        attn_av_kernel<<<dim3(Sn / 64, 1, Bn * NHn), 256>>>(attb, vb, mhab);

        gemm_nn<64><<<dim3(En / 128, NTOK / 64), 256>>>(mhab, Ol, nullptr, nullptr, projb,
                                                        NTOK, En, HIDn, 0);
        add_rmsnorm_kernel<<<NTOK, 256>>>(xb, projb, r2l, rnb);

        gemm_nn<128><<<dim3(FFn / 128, NTOK / 128), 256>>>(rnb, w1l, b1l, nullptr, hb,
                                                           NTOK, FFn, En, 1 | 2);
        // x_new = proj + (h @ w2 + b2)   (bug-faithful: input x NOT re-added)
        gemm_nn<64><<<dim3(En / 128, NTOK / 64), 256>>>(hb, w2l, b2l, projb, xb,
                                                        NTOK, En, FFn, 1 | 4);
    }

    add_rmsnorm_kernel<<<NTOK, 256>>>(xb, nullptr, final_scale, xb);

    gemm_nn<128><<<dim3(Vn / 128, NTOK / 128), 256>>>(xb, w_out, b_out, nullptr, out,
                                                      NTOK, Vn, En, 1);
    log_softmax_kernel<<<NTOK, 256>>>(out);
}

// round 3
// speedup vs baseline: 2.4656x; 2.4656x over previous
#include <cuda_runtime.h>
#include <cuda_bf16.h>
#include <math.h>
#include <stdint.h>

// ---------------- problem constants ----------------
#define Lnum 4
#define Bn   2
#define Sn   1024
#define En   1024
#define NHn  16
#define HDn  64
#define HIDn 1024
#define FFn  4096
#define Vn   32000
#define NTOK (Bn*Sn)   // 2048
#define M1   (1u<<20)  // 1024*1024

// ---------------- scratch (static device memory; no allocation) ----------------
__device__ float g_x   [NTOK*En];
__device__ float g_q   [NTOK*HIDn];
__device__ float g_k   [NTOK*HIDn];
__device__ float g_v   [NTOK*HIDn];
__device__ float g_att [(size_t)Bn*NHn*Sn*Sn];   // 128 MB
__device__ float g_mha [NTOK*HIDn];
__device__ float g_proj[NTOK*En];
__device__ float g_rn  [NTOK*En];
__device__ float g_ffh [NTOK*FFn];               // 32 MB

// activation hi/lo bf16 (max 2048 x 4096)
__device__ __nv_bfloat16 g_ahi[(size_t)NTOK*FFn];
__device__ __nv_bfloat16 g_alo[(size_t)NTOK*FFn];

// bf16 hi/lo transposed weights: [N,K] layout.
// offsets (elements): Q l*M1 | K 4M1+l*M1 | V 8M1+l*M1 | O 12M1+l*M1
//                     W1 16M1+l*4M1 | W2 32M1+l*4M1 | Wout 48M1
#define WTOT (48u*M1 + (size_t)Vn*En)
__device__ __nv_bfloat16 g_whi[WTOT];
__device__ __nv_bfloat16 g_wlo[WTOT];

// ---------------- helpers ----------------
__device__ __forceinline__ uint32_t smem_u32(const void* p) {
    uint32_t a;
    asm("{ .reg .u64 t; cvta.to.shared.u64 t, %1; cvt.u32.u64 %0, t; }" : "=r"(a) : "l"(p));
    return a;
}
__device__ __forceinline__ uint32_t pack_bf(__nv_bfloat16 a, __nv_bfloat16 b) {
    return (uint32_t)__bfloat16_as_ushort(a) | ((uint32_t)__bfloat16_as_ushort(b) << 16);
}
__device__ __forceinline__ void split2(float x, __nv_bfloat16& h, __nv_bfloat16& l) {
    h = __float2bfloat16_rn(x);
    l = __float2bfloat16_rn(x - __bfloat162float(h));
}

#define LDSM4(r, a) \
    asm volatile("ldmatrix.sync.aligned.m8n8.x4.shared.b16 {%0,%1,%2,%3}, [%4];" \
        : "=r"((r)[0]), "=r"((r)[1]), "=r"((r)[2]), "=r"((r)[3]) : "r"(a))

#define MMA16816(d, a, b0, b1) \
    asm volatile("mma.sync.aligned.m16n8k16.row.col.f32.bf16.bf16.f32 " \
        "{%0,%1,%2,%3}, {%4,%5,%6,%7}, {%8,%9}, {%0,%1,%2,%3};" \
        : "+f"((d)[0]), "+f"((d)[1]), "+f"((d)[2]), "+f"((d)[3]) \
        : "r"((a)[0]), "r"((a)[1]), "r"((a)[2]), "r"((a)[3]), "r"(b0), "r"(b1))

__device__ __forceinline__ void cp_async16(uint32_t dst, const void* src) {
    asm volatile("cp.async.cg.shared.global [%0], [%1], 16;" :: "r"(dst), "l"(src));
}

// ---------------- weight transpose + bf16 split: W[K,N] fp32 -> hi/lo [N,K] ----------------
__global__ void convert_w(const float* __restrict__ W, __nv_bfloat16* __restrict__ hi,
                          __nv_bfloat16* __restrict__ lo, int K, int N) {
    __shared__ float t[32][33];
    int n0 = blockIdx.x << 5, k0 = blockIdx.y << 5;
    int tx = threadIdx.x, ty = threadIdx.y;
    #pragma unroll
    for (int j = 0; j < 32; j += 8)
        t[ty + j][tx] = W[(size_t)(k0 + ty + j) * N + n0 + tx];
    __syncthreads();
    #pragma unroll
    for (int j = 0; j < 32; j += 8) {
        float v = t[tx][ty + j];
        __nv_bfloat16 h, l;
        split2(v, h, l);
        size_t o = (size_t)(n0 + ty + j) * K + k0 + tx;
        hi[o] = h;
        lo[o] = l;
    }
}

// ---------------- activation bf16 split (no transpose) ----------------
__global__ void split_act(const float* __restrict__ x, __nv_bfloat16* __restrict__ hi,
                          __nv_bfloat16* __restrict__ lo, int n4) {
    int i = blockIdx.x * blockDim.x + threadIdx.x;
    if (i >= n4) return;
    float4 v = ((const float4*)x)[i];
    __nv_bfloat16 h0, h1, h2, h3, l0, l1, l2, l3;
    split2(v.x, h0, l0); split2(v.y, h1, l1);
    split2(v.z, h2, l2); split2(v.w, h3, l3);
    ((uint2*)hi)[i] = make_uint2(pack_bf(h0, h1), pack_bf(h2, h3));
    ((uint2*)lo)[i] = make_uint2(pack_bf(l0, l1), pack_bf(l2, l3));
}

// ---------------- mma.sync bf16-split GEMM ----------------
// C[M,N] = A(hi/lo [M,K]) * B(hi/lo [N,K]),  fp32 accum, 3-term split.
// flags: 1 = +bias[N], 2 = relu, 4 = +add (residual, MxN)
// grid (N/128, M/128), 256 threads. smem: 2 stages x 64KB.
#define STAGE_BYTES 65536
#define GM_SMEM (2*STAGE_BYTES)
__global__ void __launch_bounds__(256, 1) gemm_mma(
    const __nv_bfloat16* __restrict__ Ahi, const __nv_bfloat16* __restrict__ Alo,
    const __nv_bfloat16* __restrict__ Bhi, const __nv_bfloat16* __restrict__ Blo,
    const float* __restrict__ bias, const float* __restrict__ add,
    float* __restrict__ C, int M, int N, int K, int flags)
{
    extern __shared__ char smem[];
    const uint32_t sb = smem_u32(smem);
    const int tid = threadIdx.x, wid = tid >> 5, lane = tid & 31;
    const int m0 = blockIdx.y << 7, n0 = blockIdx.x << 7;
    const int wm = (wid & 1) << 6;   // warp m-offset (2 rows of warps)
    const int wn = (wid >> 1) << 5;  // warp n-offset (4 cols of warps)

    const __nv_bfloat16* gAh = Ahi + (size_t)m0 * K;
    const __nv_bfloat16* gAl = Alo + (size_t)m0 * K;
    const __nv_bfloat16* gBh = Bhi + (size_t)n0 * K;
    const __nv_bfloat16* gBl = Blo + (size_t)n0 * K;

    const int nchunk = K >> 6;

    // loader thread mapping: 4 chunks of 16B per tile per thread
    const int l_row = tid >> 3;        // base row (0..31), +32*i
    const int l_ch  = tid & 7;         // 16B chunk in 128B row

    auto load_stage = [&](int s, int c) {
        const uint32_t st = sb + (uint32_t)s * STAGE_BYTES;
        const int kb = c << 6;
        const __nv_bfloat16* srcs[4] = { gAh + kb, gAl + kb, gBh + kb, gBl + kb };
        #pragma unroll
        for (int t = 0; t < 4; t++) {
            const uint32_t dstb = st + (uint32_t)t * 16384u;
            #pragma unroll
            for (int i = 0; i < 4; i++) {
                int row = l_row + (i << 5);
                uint32_t dst = dstb + (uint32_t)(row << 7) + (uint32_t)((l_ch ^ (row & 7)) << 4);
                cp_async16(dst, srcs[t] + (size_t)row * K + (l_ch << 3));
            }
        }
        asm volatile("cp.async.commit_group;" ::: "memory");
    };

    float acc[4][4][4];
    #pragma unroll
    for (int i = 0; i < 4; i++)
        #pragma unroll
        for (int j = 0; j < 4; j++)
            #pragma unroll
            for (int q = 0; q < 4; q++) acc[i][j][q] = 0.f;

    // ldmatrix lane addressing
    const int a_row = lane & 15;            // + wm + mi*16
    const int a_cb  = (lane >> 4) << 4;     // 16B half within k16
    const int b_row = (lane & 7) + ((lane >> 4) << 3);  // + wn + j*16
    const int b_cb  = ((lane >> 3) & 1) << 4;
    const uint32_t swz = (uint32_t)((lane & 7) << 4);   // row&7 == lane&7 for both

    load_stage(0, 0);

    for (int c = 0; c < nchunk; c++) {
        const int s = c & 1;
        if (c + 1 < nchunk) {
            load_stage(s ^ 1, c + 1);
            asm volatile("cp.async.wait_group 1;" ::: "memory");
        } else {
            asm volatile("cp.async.wait_group 0;" ::: "memory");
        }
        __syncthreads();

        const uint32_t st = sb + (uint32_t)s * STAGE_BYTES;
        #pragma unroll
        for (int kk = 0; kk < 4; kk++) {
            uint32_t ah[4][4], al[4][4], bh[2][4], bl[2][4];
            #pragma unroll
            for (int mi = 0; mi < 4; mi++) {
                int row = wm + (mi << 4) + a_row;
                uint32_t off = (uint32_t)(row << 7) + (((uint32_t)((kk << 5) + a_cb)) ^ swz);
                LDSM4(ah[mi], st + off);
                LDSM4(al[mi], st + 16384u + off);
            }
            #pragma unroll
            for (int j = 0; j < 2; j++) {
                int row = wn + (j << 4) + b_row;
                uint32_t off = (uint32_t)(row << 7) + (((uint32_t)((kk << 5) + b_cb)) ^ swz);
                LDSM4(bh[j], st + 32768u + off);
                LDSM4(bl[j], st + 49152u + off);
            }
            #pragma unroll
            for (int mi = 0; mi < 4; mi++) {
                #pragma unroll
                for (int nj = 0; nj < 4; nj++) {
                    uint32_t bh0 = bh[nj >> 1][(nj & 1) << 1], bh1 = bh[nj >> 1][((nj & 1) << 1) + 1];
                    uint32_t bl0 = bl[nj >> 1][(nj & 1) << 1], bl1 = bl[nj >> 1][((nj & 1) << 1) + 1];
                    MMA16816(acc[mi][nj], ah[mi], bh0, bh1);
                    MMA16816(acc[mi][nj], ah[mi], bl0, bl1);
                    MMA16816(acc[mi][nj], al[mi], bh0, bh1);
                }
            }
        }
        __syncthreads();
    }

    // epilogue
    const int er = m0 + wm + (lane >> 2);
    const int ec = n0 + wn + ((lane & 3) << 1);
    #pragma unroll
    for (int mi = 0; mi < 4; mi++) {
        #pragma unroll
        for (int half = 0; half < 2; half++) {
            int row = er + (mi << 4) + (half << 3);
            float* Cr = C + (size_t)row * N;
            const float* Ar = (flags & 4) ? (add + (size_t)row * N) : nullptr;
            #pragma unroll
            for (int nj = 0; nj < 4; nj++) {
                int col = ec + (nj << 3);
                float v0 = acc[mi][nj][half * 2 + 0];
                float v1 = acc[mi][nj][half * 2 + 1];
                if (flags & 1) { v0 += bias[col]; v1 += bias[col + 1]; }
                if (flags & 4) { v0 += Ar[col];   v1 += Ar[col + 1]; }
                if (flags & 2) { v0 = fmaxf(v0, 0.f); v1 = fmaxf(v1, 0.f); }
                *(float2*)(Cr + col) = make_float2(v0, v1);
            }
        }
    }
}

// ---------------- block reductions ----------------
__device__ __forceinline__ float blockReduceSum(float v) {
    __shared__ float sh[33];
    int lane = threadIdx.x & 31, w = threadIdx.x >> 5;
    #pragma unroll
    for (int o = 16; o > 0; o >>= 1) v += __shfl_xor_sync(0xffffffffu, v, o);
    __syncthreads();
    if (lane == 0) sh[w] = v;
    __syncthreads();
    if (w == 0) {
        v = (lane < (int)(blockDim.x >> 5)) ? sh[lane] : 0.f;
        #pragma unroll
        for (int o = 16; o > 0; o >>= 1) v += __shfl_xor_sync(0xffffffffu, v, o);
        if (lane == 0) sh[32] = v;
    }
    __syncthreads();
    return sh[32];
}
__device__ __forceinline__ float blockReduceMax(float v) {
    __shared__ float sh[33];
    int lane = threadIdx.x & 31, w = threadIdx.x >> 5;
    #pragma unroll
    for (int o = 16; o > 0; o >>= 1) v = fmaxf(v, __shfl_xor_sync(0xffffffffu, v, o));
    __syncthreads();
    if (lane == 0) sh[w] = v;
    __syncthreads();
    if (w == 0) {
        v = (lane < (int)(blockDim.x >> 5)) ? sh[lane] : -3.402823466e38f;
        #pragma unroll
        for (int o = 16; o > 0; o >>= 1) v = fmaxf(v, __shfl_xor_sync(0xffffffffu, v, o));
        if (lane == 0) sh[32] = v;
    }
    __syncthreads();
    return sh[32];
}

// ---------------- embedding ----------------
__global__ void embed_kernel(const int* __restrict__ tokens,
                             const float* __restrict__ tok,
                             const float* __restrict__ pos,
                             float* __restrict__ x) {
    int idx = blockIdx.x * blockDim.x + threadIdx.x;
    const int EV = En / 4;
    if (idx >= NTOK * EV) return;
    int bs = idx / EV, e4 = idx % EV;
    int s = bs & (Sn - 1);
    int t = tokens[bs];
    float4 a = ((const float4*)tok)[(size_t)t * EV + e4];
    float4 p = ((const float4*)pos)[(size_t)s * EV + e4];
    float4 r;
    r.x = a.x + p.x; r.y = a.y + p.y; r.z = a.z + p.z; r.w = a.w + p.w;
    ((float4*)x)[idx] = r;
}

// ---------------- attention scores ----------------
__global__ void __launch_bounds__(256) attn_scores_kernel(
    const float* __restrict__ q, const float* __restrict__ k, float* __restrict__ sc)
{
    const int bh = blockIdx.z, b = bh >> 4, h = bh & 15;
    const int s0 = blockIdx.y << 6, t0 = blockIdx.x << 6;
    __shared__ float Qs[64][68];
    __shared__ float Ks[64][68];
    const int tid = threadIdx.x, tx = tid & 15, ty = tid >> 4;
    const int lc = (tid & 15) << 2;
    const float* qb = q + (size_t)b * Sn * HIDn + h * HDn;
    const float* kb = k + (size_t)b * Sn * HIDn + h * HDn;
    #pragma unroll
    for (int p = 0; p < 4; p++) {
        int r = ty + (p << 4);
        *(float4*)&Qs[r][lc] = *(const float4*)(qb + (size_t)(s0 + r) * HIDn + lc);
        *(float4*)&Ks[r][lc] = *(const float4*)(kb + (size_t)(t0 + r) * HIDn + lc);
    }
    __syncthreads();
    float acc[4][4] = {};
    #pragma unroll
    for (int d = 0; d < 64; d += 4) {
        float4 av[4], bv[4];
        #pragma unroll
        for (int i = 0; i < 4; i++) av[i] = *(const float4*)&Qs[ty + (i << 4)][d];
        #pragma unroll
        for (int j = 0; j < 4; j++) bv[j] = *(const float4*)&Ks[tx + (j << 4)][d];
        #pragma unroll
        for (int i = 0; i < 4; i++)
            #pragma unroll
            for (int j = 0; j < 4; j++)
                acc[i][j] += av[i].x * bv[j].x + av[i].y * bv[j].y
                           + av[i].z * bv[j].z + av[i].w * bv[j].w;
    }
    const float scale = 0.125f;
    float* ob = sc + ((size_t)bh * Sn + s0) * Sn + t0;
    #pragma unroll
    for (int i = 0; i < 4; i++)
        #pragma unroll
        for (int j = 0; j < 4; j++)
            ob[(size_t)(ty + (i << 4)) * Sn + tx + (j << 4)] = acc[i][j] * scale;
}

// ---------------- softmax (UNMASKED — bug-faithful) ----------------
__global__ void softmax1024_kernel(float* __restrict__ a) {
    float* row = a + (size_t)blockIdx.x * Sn;
    int tid = threadIdx.x;
    float v[4];
    #pragma unroll
    for (int j = 0; j < 4; j++) v[j] = row[tid + j * 256];
    float m = fmaxf(fmaxf(v[0], v[1]), fmaxf(v[2], v[3]));
    m = blockReduceMax(m);
    float s = 0.f;
    #pragma unroll
    for (int j = 0; j < 4; j++) { v[j] = __expf(v[j] - m); s += v[j]; }
    s = blockReduceSum(s);
    float inv = 1.f / s;
    #pragma unroll
    for (int j = 0; j < 4; j++) row[tid + j * 256] = v[j] * inv;
}

// ---------------- attn . V ----------------
__global__ void __launch_bounds__(256) attn_av_kernel(
    const float* __restrict__ attn, const float* __restrict__ v, float* __restrict__ mha)
{
    const int bh = blockIdx.z, b = bh >> 4, h = bh & 15;
    const int t0 = blockIdx.x << 6;
    __shared__ float As[64][68];
    __shared__ float Vs[64][68];
    const int tid = threadIdx.x, tx = tid & 15, ty = tid >> 4;
    const int lc = (tid & 15) << 2;
    const float* ab = attn + (size_t)bh * Sn * Sn;
    const float* vb = v + (size_t)b * Sn * HIDn + h * HDn;
    float acc[4][4] = {};
    for (int c0 = 0; c0 < Sn; c0 += 64) {
        #pragma unroll
        for (int p = 0; p < 4; p++) {
            int r = ty + (p << 4);
            *(float4*)&As[r][lc] = *(const float4*)(ab + (size_t)(c0 + r) * Sn + t0 + lc);
            *(float4*)&Vs[r][lc] = *(const float4*)(vb + (size_t)(c0 + r) * HIDn + lc);
        }
        __syncthreads();
        #pragma unroll
        for (int s = 0; s < 64; s++) {
            float a[4];
            #pragma unroll
            for (int i = 0; i < 4; i++) a[i] = As[s][ty + (i << 4)];
            float4 bv = *(const float4*)&Vs[s][tx << 2];
            #pragma unroll
            for (int i = 0; i < 4; i++) {
                acc[i][0] = fmaf(a[i], bv.x, acc[i][0]);
                acc[i][1] = fmaf(a[i], bv.y, acc[i][1]);
                acc[i][2] = fmaf(a[i], bv.z, acc[i][2]);
                acc[i][3] = fmaf(a[i], bv.w, acc[i][3]);
            }
        }
        __syncthreads();
    }
    float* ob = mha + (size_t)b * Sn * HIDn + h * HDn;
    #pragma unroll
    for (int i = 0; i < 4; i++) {
        float4 w;
        w.x = acc[i][0]; w.y = acc[i][1]; w.z = acc[i][2]; w.w = acc[i][3];
        *(float4*)(ob + (size_t)(t0 + ty + (i << 4)) * HIDn + (tx << 2)) = w;
    }
}

// ---------------- rmsnorm ----------------
__global__ void add_rmsnorm_kernel(const float* __restrict__ x, const float* __restrict__ add,
                                   const float* __restrict__ scale, float* __restrict__ out)
{
    int row = blockIdx.x, tid = threadIdx.x;
    const float* xr = x + (size_t)row * En;
    const float* ar = add ? add + (size_t)row * En : nullptr;
    float v[4]; float ss = 0.f;
    #pragma unroll
    for (int j = 0; j < 4; j++) {
        int e = tid + j * 256;
        float t = xr[e];
        if (ar) t += ar[e];
        v[j] = t;
        ss += t * t;
    }
    ss = blockReduceSum(ss);
    float r = rsqrtf(ss * (1.f / En) + 1e-6f);
    float* orow = out + (size_t)row * En;
    #pragma unroll
    for (int j = 0; j < 4; j++) {
        int e = tid + j * 256;
        orow[e] = v[j] * r * scale[e];
    }
}

// ---------------- log_softmax ----------------
__global__ void log_softmax_kernel(float* __restrict__ a) {
    float* row = a + (size_t)blockIdx.x * Vn;
    int tid = threadIdx.x;
    float m = -3.402823466e38f;
    for (int i = tid; i < Vn; i += 256) m = fmaxf(m, row[i]);
    m = blockReduceMax(m);
    float s = 0.f;
    for (int i = tid; i < Vn; i += 256) s += __expf(row[i] - m);
    s = blockReduceSum(s);
    float lse = m + logf(s);
    for (int i = tid; i < Vn; i += 256) row[i] -= lse;
}

// ---------------- launch ----------------
extern "C" void kernel_launch(void* const* d_in, const int* in_sizes, int n_in,
                              void* d_out, int out_size) {
    const int*   tokens      = (const int*)  d_in[0];
    const float* tok_embed   = (const float*)d_in[1];
    const float* pos_embed   = (const float*)d_in[2];
    const float* Qw          = (const float*)d_in[3];
    const float* Kw          = (const float*)d_in[4];
    const float* Vw          = (const float*)d_in[5];
    const float* Ow          = (const float*)d_in[6];
    const float* rs2         = (const float*)d_in[7];
    const float* w1          = (const float*)d_in[8];
    const float* b1          = (const float*)d_in[9];
    const float* w2          = (const float*)d_in[10];
    const float* b2          = (const float*)d_in[11];
    const float* final_scale = (const float*)d_in[12];
    const float* w_out       = (const float*)d_in[13];
    const float* b_out       = (const float*)d_in[14];
    float* out = (float*)d_out;

    float *xb, *qb, *kb, *vb, *attb, *mhab, *projb, *rnb, *hb;
    __nv_bfloat16 *whi, *wlo, *ahi, *alo;
    cudaGetSymbolAddress((void**)&xb,    g_x);
    cudaGetSymbolAddress((void**)&qb,    g_q);
    cudaGetSymbolAddress((void**)&kb,    g_k);
    cudaGetSymbolAddress((void**)&vb,    g_v);
    cudaGetSymbolAddress((void**)&attb,  g_att);
    cudaGetSymbolAddress((void**)&mhab,  g_mha);
    cudaGetSymbolAddress((void**)&projb, g_proj);
    cudaGetSymbolAddress((void**)&rnb,   g_rn);
    cudaGetSymbolAddress((void**)&hb,    g_ffh);
    cudaGetSymbolAddress((void**)&whi,   g_whi);
    cudaGetSymbolAddress((void**)&wlo,   g_wlo);
    cudaGetSymbolAddress((void**)&ahi,   g_ahi);
    cudaGetSymbolAddress((void**)&alo,   g_alo);

    cudaFuncSetAttribute(gemm_mma, cudaFuncAttributeMaxDynamicSharedMemorySize, GM_SMEM);

    // ---- weight conversion: transpose + bf16 split ----
    dim3 cb(32, 8);
    for (int l = 0; l < Lnum; l++) {
        convert_w<<<dim3(32, 32), cb>>>(Qw + (size_t)l * M1, whi + (size_t)l * M1,
                                        wlo + (size_t)l * M1, En, HIDn);
        convert_w<<<dim3(32, 32), cb>>>(Kw + (size_t)l * M1, whi + 4 * (size_t)M1 + (size_t)l * M1,
                                        wlo + 4 * (size_t)M1 + (size_t)l * M1, En, HIDn);
        convert_w<<<dim3(32, 32), cb>>>(Vw + (size_t)l * M1, whi + 8 * (size_t)M1 + (size_t)l * M1,
                                        wlo + 8 * (size_t)M1 + (size_t)l * M1, En, HIDn);
        convert_w<<<dim3(32, 32), cb>>>(Ow + (size_t)l * M1, whi + 12 * (size_t)M1 + (size_t)l * M1,
                                        wlo + 12 * (size_t)M1 + (size_t)l * M1, HIDn, En);
        convert_w<<<dim3(128, 32), cb>>>(w1 + (size_t)l * 4 * M1,
                                         whi + 16 * (size_t)M1 + (size_t)l * 4 * M1,
                                         wlo + 16 * (size_t)M1 + (size_t)l * 4 * M1, En, FFn);
        convert_w<<<dim3(32, 128), cb>>>(w2 + (size_t)l * 4 * M1,
                                         whi + 32 * (size_t)M1 + (size_t)l * 4 * M1,
                                         wlo + 32 * (size_t)M1 + (size_t)l * 4 * M1, FFn, En);
    }
    convert_w<<<dim3(Vn / 32, 32), cb>>>(w_out, whi + 48 * (size_t)M1, wlo + 48 * (size_t)M1, En, Vn);

    embed_kernel<<<(NTOK * (En / 4) + 255) / 256, 256>>>(tokens, tok_embed, pos_embed, xb);

    const int n4_1k = NTOK * En / 4;   // 2048x1024 / 4
    const int n4_4k = NTOK * FFn / 4;  // 2048x4096 / 4

    for (int l = 0; l < Lnum; l++) {
        const __nv_bfloat16 *Qh = whi + (size_t)l * M1,                   *Ql2 = wlo + (size_t)l * M1;
        const __nv_bfloat16 *Kh = whi + 4 * (size_t)M1 + (size_t)l * M1,  *Kl2 = wlo + 4 * (size_t)M1 + (size_t)l * M1;
        const __nv_bfloat16 *Vh = whi + 8 * (size_t)M1 + (size_t)l * M1,  *Vl2 = wlo + 8 * (size_t)M1 + (size_t)l * M1;
        const __nv_bfloat16 *Oh = whi + 12 * (size_t)M1 + (size_t)l * M1, *Ol2 = wlo + 12 * (size_t)M1 + (size_t)l * M1;
        const __nv_bfloat16 *W1h = whi + 16 * (size_t)M1 + (size_t)l * 4 * M1,
                            *W1l = wlo + 16 * (size_t)M1 + (size_t)l * 4 * M1;
        const __nv_bfloat16 *W2h = whi + 32 * (size_t)M1 + (size_t)l * 4 * M1,
                            *W2l = wlo + 32 * (size_t)M1 + (size_t)l * 4 * M1;
        const float* r2l = rs2 + (size_t)l * En;
        const float* b1l = b1 + (size_t)l * FFn;
        const float* b2l = b2 + (size_t)l * En;

        dim3 g1024(HIDn / 128, NTOK / 128);
        // split x once; reused by Q,K,V gemms
        split_act<<<(n4_1k + 255) / 256, 256>>>(xb, ahi, alo, n4_1k);
        gemm_mma<<<g1024, 256, GM_SMEM>>>(ahi, alo, Qh, Ql2, nullptr, nullptr, qb, NTOK, HIDn, En, 0);
        gemm_mma<<<g1024, 256, GM_SMEM>>>(ahi, alo, Kh, Kl2, nullptr, nullptr, kb, NTOK, HIDn, En, 0);
        gemm_mma<<<g1024, 256, GM_SMEM>>>(ahi, alo, Vh, Vl2, nullptr, nullptr, vb, NTOK, HIDn, En, 0);

        attn_scores_kernel<<<dim3(Sn / 64, Sn / 64, Bn * NHn), 256>>>(qb, kb, attb);
        softmax1024_kernel<<<Bn * NHn * Sn, 256>>>(attb);
        attn_av_kernel<<<dim3(Sn / 64, 1, Bn * NHn), 256>>>(attb, vb, mhab);

        split_act<<<(n4_1k + 255) / 256, 256>>>(mhab, ahi, alo, n4_1k);
        gemm_mma<<<g1024, 256, GM_SMEM>>>(ahi, alo, Oh, Ol2, nullptr, nullptr, projb, NTOK, En, HIDn, 0);
        add_rmsnorm_kernel<<<NTOK, 256>>>(xb, projb, r2l, rnb);

        split_act<<<(n4_1k + 255) / 256, 256>>>(rnb, ahi, alo, n4_1k);
        gemm_mma<<<dim3(FFn / 128, NTOK / 128), 256, GM_SMEM>>>(ahi, alo, W1h, W1l, b1l, nullptr,
                                                                hb, NTOK, FFn, En, 1 | 2);
        split_act<<<(n4_4k + 255) / 256, 256>>>(hb, ahi, alo, n4_4k);
        gemm_mma<<<g1024, 256, GM_SMEM>>>(ahi, alo, W2h, W2l, b2l, projb, xb, NTOK, En, FFn, 1 | 4);
    }

    add_rmsnorm_kernel<<<NTOK, 256>>>(xb, nullptr, final_scale, xb);

    split_act<<<(n4_1k + 255) / 256, 256>>>(xb, ahi, alo, n4_1k);
    gemm_mma<<<dim3(Vn / 128, NTOK / 128), 256, GM_SMEM>>>(ahi, alo, whi + 48 * (size_t)M1,
                                                           wlo + 48 * (size_t)M1, b_out, nullptr,
                                                           out, NTOK, Vn, En, 1);
    log_softmax_kernel<<<NTOK, 256>>>(out);
}

// round 5
// speedup vs baseline: 2.6161x; 1.0610x over previous
#include <cuda_runtime.h>
#include <cuda_bf16.h>
#include <math.h>
#include <stdint.h>

// ---------------- problem constants ----------------
#define Lnum 4
#define Bn   2
#define Sn   1024
#define En   1024
#define NHn  16
#define HDn  64
#define HIDn 1024
#define FFn  4096
#define Vn   32000
#define NTOK (Bn*Sn)   // 2048
#define M1   (1u<<20)  // 1024*1024

typedef __nv_bfloat16 bf16;

// ---------------- scratch (static device memory; no allocation) ----------------
__device__ float g_x   [NTOK*En];                 // residual stream fp32
__device__ float g_proj[NTOK*En];                 // attn projection fp32
__device__ float g_att [(size_t)Bn*NHn*Sn*Sn];    // scoresT fp32, 128 MB

__device__ bf16 g_pt [(size_t)Bn*NHn*Sn*Sn];      // probsT bf16, 64 MB
__device__ bf16 g_xh[NTOK*En],  g_xl[NTOK*En];    // x hi/lo
__device__ bf16 g_qh[NTOK*HIDn], g_ql[NTOK*HIDn]; // q head-major [b,h,s,d]
__device__ bf16 g_kh[NTOK*HIDn], g_kl[NTOK*HIDn]; // k head-major
__device__ bf16 g_vt[NTOK*HIDn];                  // v transposed [b,h,d,s]
__device__ bf16 g_mh[NTOK*En],  g_ml[NTOK*En];    // mha hi/lo (token-major)
__device__ bf16 g_rh[NTOK*En],  g_rl[NTOK*En];    // rmsnorm out hi/lo
__device__ bf16 g_hh[(size_t)NTOK*FFn], g_hl[(size_t)NTOK*FFn]; // FF hidden hi/lo

// bf16 hi/lo transposed weights: [N,K] layout.
#define WTOT (48u*M1 + (size_t)Vn*En)
__device__ bf16 g_whi[WTOT];
__device__ bf16 g_wlo[WTOT];

// ---------------- helpers ----------------
__device__ __forceinline__ uint32_t smem_u32(const void* p) {
    uint32_t a;
    asm("{ .reg .u64 t; cvta.to.shared.u64 t, %1; cvt.u32.u64 %0, t; }" : "=r"(a) : "l"(p));
    return a;
}
__device__ __forceinline__ uint32_t pack_bf(bf16 a, bf16 b) {
    return (uint32_t)__bfloat16_as_ushort(a) | ((uint32_t)__bfloat16_as_ushort(b) << 16);
}
__device__ __forceinline__ void split2(float x, bf16& h, bf16& l) {
    h = __float2bfloat16_rn(x);
    l = __float2bfloat16_rn(x - __bfloat162float(h));
}

#define LDSM4(r, a) \
    asm volatile("ldmatrix.sync.aligned.m8n8.x4.shared.b16 {%0,%1,%2,%3}, [%4];" \
        : "=r"((r)[0]), "=r"((r)[1]), "=r"((r)[2]), "=r"((r)[3]) : "r"(a))

#define MMA16816(d, a, b0, b1) \
    asm volatile("mma.sync.aligned.m16n8k16.row.col.f32.bf16.bf16.f32 " \
        "{%0,%1,%2,%3}, {%4,%5,%6,%7}, {%8,%9}, {%0,%1,%2,%3};" \
        : "+f"((d)[0]), "+f"((d)[1]), "+f"((d)[2]), "+f"((d)[3]) \
        : "r"((a)[0]), "r"((a)[1]), "r"((a)[2]), "r"((a)[3]), "r"(b0), "r"(b1))

__device__ __forceinline__ void cp_async16(uint32_t dst, const void* src) {
    asm volatile("cp.async.cg.shared.global [%0], [%1], 16;" :: "r"(dst), "l"(src));
}

// ---------------- weight transpose + bf16 split: W[K,N] fp32 -> hi/lo [N,K] ----------------
// grid (N/32, K/64), block (32, 8)
__global__ void convert_w(const float* __restrict__ W, bf16* __restrict__ hi,
                          bf16* __restrict__ lo, int K, int N) {
    __shared__ float t[64][33];
    int n0 = blockIdx.x << 5, k0 = blockIdx.y << 6;
    int tx = threadIdx.x, ty = threadIdx.y;
    #pragma unroll
    for (int j = 0; j < 64; j += 8)
        t[ty + j][tx] = W[(size_t)(k0 + ty + j) * N + n0 + tx];
    __syncthreads();
    #pragma unroll
    for (int j = 0; j < 32; j += 8) {
        int n = ty + j;
        float v0 = t[2 * tx][n], v1 = t[2 * tx + 1][n];
        bf16 h0, l0, h1, l1;
        split2(v0, h0, l0); split2(v1, h1, l1);
        size_t o = (size_t)(n0 + n) * K + k0 + 2 * tx;
        *(uint32_t*)&hi[o] = pack_bf(h0, h1);
        *(uint32_t*)&lo[o] = pack_bf(l0, l1);
    }
}

// ---------------- mma.sync bf16-split GEMM ----------------
// C[M,N] = A(hi/lo [M,K]) * B(hi/lo [N,K]),  fp32 accum, 3-term split.
// flags: 1 = +bias[N], 2 = relu, 4 = +add (residual, MxN)
// omode: 0 = C fp32 only; 1 = C fp32 + Chi/Clo token-major; 2 = Chi/Clo only;
//        3 = head-major hi/lo q/k [b,h,s,d]; 4 = transposed bf16 v [b,h,d,s]
#define STAGE_BYTES 65536
#define GM_SMEM (2*STAGE_BYTES)
__global__ void __launch_bounds__(256, 1) gemm_mma(
    const bf16* __restrict__ Ahi, const bf16* __restrict__ Alo,
    const bf16* __restrict__ Bhi, const bf16* __restrict__ Blo,
    const float* __restrict__ bias, const float* __restrict__ add,
    float* __restrict__ C, bf16* __restrict__ Chi, bf16* __restrict__ Clo,
    int M, int N, int K, int flags, int omode)
{
    extern __shared__ char smem[];
    const uint32_t sb = smem_u32(smem);
    const int tid = threadIdx.x, wid = tid >> 5, lane = tid & 31;
    const int m0 = blockIdx.y << 7, n0 = blockIdx.x << 7;
    const int wm = (wid & 1) << 6;
    const int wn = (wid >> 1) << 5;

    const bf16* gAh = Ahi + (size_t)m0 * K;
    const bf16* gAl = Alo + (size_t)m0 * K;
    const bf16* gBh = Bhi + (size_t)n0 * K;
    const bf16* gBl = Blo + (size_t)n0 * K;

    const int nchunk = K >> 6;
    const int l_row = tid >> 3;
    const int l_ch  = tid & 7;

    auto load_stage = [&](int s, int c) {
        const uint32_t st = sb + (uint32_t)s * STAGE_BYTES;
        const int kb = c << 6;
        const bf16* srcs[4] = { gAh + kb, gAl + kb, gBh + kb, gBl + kb };
        #pragma unroll
        for (int t = 0; t < 4; t++) {
            const uint32_t dstb = st + (uint32_t)t * 16384u;
            #pragma unroll
            for (int i = 0; i < 4; i++) {
                int row = l_row + (i << 5);
                uint32_t dst = dstb + (uint32_t)(row << 7) + (uint32_t)((l_ch ^ (row & 7)) << 4);
                cp_async16(dst, srcs[t] + (size_t)row * K + (l_ch << 3));
            }
        }
        asm volatile("cp.async.commit_group;" ::: "memory");
    };

    float acc[4][4][4];
    #pragma unroll
    for (int i = 0; i < 4; i++)
        #pragma unroll
        for (int j = 0; j < 4; j++)
            #pragma unroll
            for (int q = 0; q < 4; q++) acc[i][j][q] = 0.f;

    const int a_row = lane & 15;
    const int a_cb  = (lane >> 4) << 4;
    const int b_row = (lane & 7) + ((lane >> 4) << 3);
    const int b_cb  = ((lane >> 3) & 1) << 4;
    const uint32_t swz = (uint32_t)((lane & 7) << 4);

    load_stage(0, 0);

    for (int c = 0; c < nchunk; c++) {
        const int s = c & 1;
        if (c + 1 < nchunk) {
            load_stage(s ^ 1, c + 1);
            asm volatile("cp.async.wait_group 1;" ::: "memory");
        } else {
            asm volatile("cp.async.wait_group 0;" ::: "memory");
        }
        __syncthreads();

        const uint32_t st = sb + (uint32_t)s * STAGE_BYTES;
        #pragma unroll
        for (int kk = 0; kk < 4; kk++) {
            uint32_t ah[4][4], al[4][4], bh[2][4], bl[2][4];
            #pragma unroll
            for (int mi = 0; mi < 4; mi++) {
                int row = wm + (mi << 4) + a_row;
                uint32_t off = (uint32_t)(row << 7) + (((uint32_t)((kk << 5) + a_cb)) ^ swz);
                LDSM4(ah[mi], st + off);
                LDSM4(al[mi], st + 16384u + off);
            }
            #pragma unroll
            for (int j = 0; j < 2; j++) {
                int row = wn + (j << 4) + b_row;
                uint32_t off = (uint32_t)(row << 7) + (((uint32_t)((kk << 5) + b_cb)) ^ swz);
                LDSM4(bh[j], st + 32768u + off);
                LDSM4(bl[j], st + 49152u + off);
            }
            #pragma unroll
            for (int mi = 0; mi < 4; mi++) {
                #pragma unroll
                for (int nj = 0; nj < 4; nj++) {
                    uint32_t bh0 = bh[nj >> 1][(nj & 1) << 1], bh1 = bh[nj >> 1][((nj & 1) << 1) + 1];
                    uint32_t bl0 = bl[nj >> 1][(nj & 1) << 1], bl1 = bl[nj >> 1][((nj & 1) << 1) + 1];
                    MMA16816(acc[mi][nj], ah[mi], bh0, bh1);
                    MMA16816(acc[mi][nj], ah[mi], bl0, bl1);
                    MMA16816(acc[mi][nj], al[mi], bh0, bh1);
                }
            }
        }
        __syncthreads();
    }

    // epilogue
    const int er = m0 + wm + (lane >> 2);
    const int ec = n0 + wn + ((lane & 3) << 1);
    #pragma unroll
    for (int mi = 0; mi < 4; mi++) {
        #pragma unroll
        for (int half = 0; half < 2; half++) {
            int row = er + (mi << 4) + (half << 3);
            const float* Ar = (flags & 4) ? (add + (size_t)row * N) : nullptr;
            int bidx = row >> 10, srow = row & 1023;
            #pragma unroll
            for (int nj = 0; nj < 4; nj++) {
                int col = ec + (nj << 3);
                float v0 = acc[mi][nj][half * 2 + 0];
                float v1 = acc[mi][nj][half * 2 + 1];
                if (flags & 1) { v0 += bias[col]; v1 += bias[col + 1]; }
                if (flags & 4) { v0 += Ar[col];   v1 += Ar[col + 1]; }
                if (flags & 2) { v0 = fmaxf(v0, 0.f); v1 = fmaxf(v1, 0.f); }
                if (omode <= 1)
                    *(float2*)(C + (size_t)row * N + col) = make_float2(v0, v1);
                if (omode == 1 || omode == 2) {
                    bf16 h0, l0, h1, l1;
                    split2(v0, h0, l0); split2(v1, h1, l1);
                    *(uint32_t*)&Chi[(size_t)row * N + col] = pack_bf(h0, h1);
                    *(uint32_t*)&Clo[(size_t)row * N + col] = pack_bf(l0, l1);
                } else if (omode == 3) {
                    int h = col >> 6, d = col & 63;
                    size_t dst = (((size_t)((bidx << 4) + h) << 10) + srow) * 64 + d;
                    bf16 h0, l0, h1, l1;
                    split2(v0, h0, l0); split2(v1, h1, l1);
                    *(uint32_t*)&Chi[dst] = pack_bf(h0, h1);
                    *(uint32_t*)&Clo[dst] = pack_bf(l0, l1);
                } else if (omode == 4) {
                    int h = col >> 6, d = col & 63;
                    size_t hb = (size_t)((bidx << 4) + h) << 6;
                    Chi[(hb + d) * 1024 + srow]     = __float2bfloat16_rn(v0);
                    Chi[(hb + d + 1) * 1024 + srow] = __float2bfloat16_rn(v1);
                }
            }
        }
    }
}

// ---------------- scoresT: scT[bh][t][s] = 0.125 * k[bh,t,:].q[bh,s,:]  (3-term) ----------------
// grid (S/128, S/128, 32), block 256, smem 64KB
#define SC_SMEM 65536
__global__ void __launch_bounds__(256, 1) scoresT_mma(
    const bf16* __restrict__ Kh, const bf16* __restrict__ Kl,
    const bf16* __restrict__ Qh, const bf16* __restrict__ Ql,
    float* __restrict__ scT)
{
    extern __shared__ char smem[];
    const uint32_t sb = smem_u32(smem);
    const int tid = threadIdx.x, wid = tid >> 5, lane = tid & 31;
    const int bh = blockIdx.z;
    const int t0 = blockIdx.y << 7, s0 = blockIdx.x << 7;
    const size_t hb = (size_t)bh << 16;
    const bf16* srcs[4] = {
        Kh + hb + (size_t)t0 * 64, Kl + hb + (size_t)t0 * 64,
        Qh + hb + (size_t)s0 * 64, Ql + hb + (size_t)s0 * 64 };

    {
        const int l_row = tid >> 3, l_ch = tid & 7;
        #pragma unroll
        for (int t = 0; t < 4; t++) {
            #pragma unroll
            for (int i = 0; i < 4; i++) {
                int row = l_row + (i << 5);
                uint32_t dst = sb + (uint32_t)t * 16384u + (uint32_t)(row << 7)
                             + (uint32_t)((l_ch ^ (row & 7)) << 4);
                cp_async16(dst, srcs[t] + (size_t)row * 64 + (l_ch << 3));
            }
        }
        asm volatile("cp.async.commit_group;" ::: "memory");
        asm volatile("cp.async.wait_group 0;" ::: "memory");
    }
    __syncthreads();

    const int wm = (wid & 1) << 6, wn = (wid >> 1) << 5;
    float acc[4][4][4];
    #pragma unroll
    for (int i = 0; i < 4; i++)
        #pragma unroll
        for (int j = 0; j < 4; j++)
            #pragma unroll
            for (int q = 0; q < 4; q++) acc[i][j][q] = 0.f;

    const int a_row = lane & 15, a_cb = (lane >> 4) << 4;
    const int b_row = (lane & 7) + ((lane >> 4) << 3), b_cb = ((lane >> 3) & 1) << 4;
    const uint32_t swz = (uint32_t)((lane & 7) << 4);

    #pragma unroll
    for (int kk = 0; kk < 4; kk++) {
        uint32_t ah[4][4], al[4][4], bh2[2][4], bl2[2][4];
        #pragma unroll
        for (int mi = 0; mi < 4; mi++) {
            int row = wm + (mi << 4) + a_row;
            uint32_t off = (uint32_t)(row << 7) + (((uint32_t)((kk << 5) + a_cb)) ^ swz);
            LDSM4(ah[mi], sb + off);
            LDSM4(al[mi], sb + 16384u + off);
        }
        #pragma unroll
        for (int j = 0; j < 2; j++) {
            int row = wn + (j << 4) + b_row;
            uint32_t off = (uint32_t)(row << 7) + (((uint32_t)((kk << 5) + b_cb)) ^ swz);
            LDSM4(bh2[j], sb + 32768u + off);
            LDSM4(bl2[j], sb + 49152u + off);
        }
        #pragma unroll
        for (int mi = 0; mi < 4; mi++) {
            #pragma unroll
            for (int nj = 0; nj < 4; nj++) {
                uint32_t b0 = bh2[nj >> 1][(nj & 1) << 1], b1 = bh2[nj >> 1][((nj & 1) << 1) + 1];
                uint32_t c0 = bl2[nj >> 1][(nj & 1) << 1], c1 = bl2[nj >> 1][((nj & 1) << 1) + 1];
                MMA16816(acc[mi][nj], ah[mi], b0, b1);
                MMA16816(acc[mi][nj], ah[mi], c0, c1);
                MMA16816(acc[mi][nj], al[mi], b0, b1);
            }
        }
    }

    float* ob = scT + ((size_t)bh << 20);
    const int er = t0 + wm + (lane >> 2);
    const int ec = s0 + wn + ((lane & 3) << 1);
    #pragma unroll
    for (int mi = 0; mi < 4; mi++) {
        #pragma unroll
        for (int half = 0; half < 2; half++) {
            int row = er + (mi << 4) + (half << 3);
            #pragma unroll
            for (int nj = 0; nj < 4; nj++) {
                int col = ec + (nj << 3);
                *(float2*)(ob + (size_t)row * Sn + col) =
                    make_float2(acc[mi][nj][half * 2] * 0.125f,
                                acc[mi][nj][half * 2 + 1] * 0.125f);
            }
        }
    }
}

// ---------------- column softmax: pT[t][s] = softmax_t(scT[t][s])  (UNMASKED, bug-faithful) ----------------
// grid (S/128, 32), block 128; each thread owns one column s.
__global__ void col_softmax(const float* __restrict__ scT, bf16* __restrict__ pT) {
    const int bh = blockIdx.y;
    const int s = (blockIdx.x << 7) + threadIdx.x;
    const float* base = scT + ((size_t)bh << 20) + s;
    float m = -3.402823466e38f, sum = 0.f;
    for (int t = 0; t < Sn; t++) {
        float x = base[(size_t)t << 10];
        float nm = fmaxf(m, x);
        sum = sum * __expf(m - nm) + __expf(x - nm);
        m = nm;
    }
    float inv = 1.f / sum;
    bf16* ob = pT + ((size_t)bh << 20) + s;
    for (int t = 0; t < Sn; t++) {
        float x = base[(size_t)t << 10];
        ob[(size_t)t << 10] = __float2bfloat16_rn(__expf(x - m) * inv);
    }
}

// ---------------- AV: mha[b,t,h,d] = sum_s pT[bh,t,s] * vT[bh,d,s]  (single-term bf16) ----------------
// grid (S/128, 32), block 256, smem 96KB
#define AV_STAGE 49152
#define AV_SMEM (2*AV_STAGE)
__global__ void __launch_bounds__(256, 1) av_mma(
    const bf16* __restrict__ pT, const bf16* __restrict__ vT,
    bf16* __restrict__ Mh, bf16* __restrict__ Ml)
{
    extern __shared__ char smem[];
    const uint32_t sb = smem_u32(smem);
    const int tid = threadIdx.x, wid = tid >> 5, lane = tid & 31;
    const int bh = blockIdx.y, t0 = blockIdx.x << 7;
    const bf16* gA = pT + ((size_t)bh << 20) + (size_t)t0 * 1024;
    const bf16* gB = vT + ((size_t)bh << 16);

    auto load_stage = [&](int s, int c) {
        const uint32_t st = sb + (uint32_t)s * AV_STAGE;
        const int kb = c << 7;
        #pragma unroll
        for (int i = 0; i < 8; i++) {
            int idx = tid + (i << 8);
            int row = idx >> 4, ch = idx & 15;
            uint32_t dst = st + (uint32_t)(row << 8) + (uint32_t)((ch ^ (row & 7)) << 4);
            cp_async16(dst, gA + (size_t)row * 1024 + kb + (ch << 3));
        }
        #pragma unroll
        for (int i = 0; i < 4; i++) {
            int idx = tid + (i << 8);
            int row = idx >> 4, ch = idx & 15;
            uint32_t dst = st + 32768u + (uint32_t)(row << 8) + (uint32_t)((ch ^ (row & 7)) << 4);
            cp_async16(dst, gB + (size_t)row * 1024 + kb + (ch << 3));
        }
        asm volatile("cp.async.commit_group;" ::: "memory");
    };

    const int wm = (wid & 3) << 5, wn = (wid >> 2) << 5;
    float acc[2][4][4];
    #pragma unroll
    for (int i = 0; i < 2; i++)
        #pragma unroll
        for (int j = 0; j < 4; j++)
            #pragma unroll
            for (int q = 0; q < 4; q++) acc[i][j][q] = 0.f;

    const int a_row = lane & 15, a_cb = (lane >> 4) << 4;
    const int b_row = (lane & 7) + ((lane >> 4) << 3), b_cb = ((lane >> 3) & 1) << 4;
    const uint32_t swz = (uint32_t)((lane & 7) << 4);

    load_stage(0, 0);
    for (int c = 0; c < 8; c++) {
        const int s = c & 1;
        if (c + 1 < 8) {
            load_stage(s ^ 1, c + 1);
            asm volatile("cp.async.wait_group 1;" ::: "memory");
        } else {
            asm volatile("cp.async.wait_group 0;" ::: "memory");
        }
        __syncthreads();

        const uint32_t st = sb + (uint32_t)s * AV_STAGE;
        #pragma unroll
        for (int kk = 0; kk < 8; kk++) {
            uint32_t af[2][4], bf2[2][4];
            #pragma unroll
            for (int mi = 0; mi < 2; mi++) {
                int row = wm + (mi << 4) + a_row;
                uint32_t off = (uint32_t)(row << 8) + (((uint32_t)((kk << 5) + a_cb)) ^ swz);
                LDSM4(af[mi], st + off);
            }
            #pragma unroll
            for (int j = 0; j < 2; j++) {
                int row = wn + (j << 4) + b_row;
                uint32_t off = (uint32_t)(row << 8) + (((uint32_t)((kk << 5) + b_cb)) ^ swz);
                LDSM4(bf2[j], st + 32768u + off);
            }
            #pragma unroll
            for (int mi = 0; mi < 2; mi++) {
                #pragma unroll
                for (int nj = 0; nj < 4; nj++) {
                    MMA16816(acc[mi][nj], af[mi],
                             bf2[nj >> 1][(nj & 1) << 1], bf2[nj >> 1][((nj & 1) << 1) + 1]);
                }
            }
        }
        __syncthreads();
    }

    const int b = bh >> 4, h = bh & 15;
    const int er = t0 + wm + (lane >> 2);
    const int ec = wn + ((lane & 3) << 1);
    #pragma unroll
    for (int mi = 0; mi < 2; mi++) {
        #pragma unroll
        for (int half = 0; half < 2; half++) {
            int t = er + (mi << 4) + (half << 3);
            size_t rowbase = ((size_t)(b << 10) + t) * 1024 + (h << 6);
            #pragma unroll
            for (int nj = 0; nj < 4; nj++) {
                int col = ec + (nj << 3);
                bf16 h0, l0, h1, l1;
                split2(acc[mi][nj][half * 2], h0, l0);
                split2(acc[mi][nj][half * 2 + 1], h1, l1);
                *(uint32_t*)&Mh[rowbase + col] = pack_bf(h0, h1);
                *(uint32_t*)&Ml[rowbase + col] = pack_bf(l0, l1);
            }
        }
    }
}

// ---------------- block reductions ----------------
__device__ __forceinline__ float blockReduceSum(float v) {
    __shared__ float sh[33];
    int lane = threadIdx.x & 31, w = threadIdx.x >> 5;
    #pragma unroll
    for (int o = 16; o > 0; o >>= 1) v += __shfl_xor_sync(0xffffffffu, v, o);
    __syncthreads();
    if (lane == 0) sh[w] = v;
    __syncthreads();
    if (w == 0) {
        v = (lane < (int)(blockDim.x >> 5)) ? sh[lane] : 0.f;
        #pragma unroll
        for (int o = 16; o > 0; o >>= 1) v += __shfl_xor_sync(0xffffffffu, v, o);
        if (lane == 0) sh[32] = v;
    }
    __syncthreads();
    return sh[32];
}
__device__ __forceinline__ float blockReduceMax(float v) {
    __shared__ float sh[33];
    int lane = threadIdx.x & 31, w = threadIdx.x >> 5;
    #pragma unroll
    for (int o = 16; o > 0; o >>= 1) v = fmaxf(v, __shfl_xor_sync(0xffffffffu, v, o));
    __syncthreads();
    if (lane == 0) sh[w] = v;
    __syncthreads();
    if (w == 0) {
        v = (lane < (int)(blockDim.x >> 5)) ? sh[lane] : -3.402823466e38f;
        #pragma unroll
        for (int o = 16; o > 0; o >>= 1) v = fmaxf(v, __shfl_xor_sync(0xffffffffu, v, o));
        if (lane == 0) sh[32] = v;
    }
    __syncthreads();
    return sh[32];
}

// ---------------- embedding: x fp32 + hi/lo bf16 ----------------
__global__ void embed_kernel(const int* __restrict__ tokens,
                             const float* __restrict__ tok,
                             const float* __restrict__ pos,
                             float* __restrict__ x,
                             bf16* __restrict__ xh, bf16* __restrict__ xl) {
    int idx = blockIdx.x * blockDim.x + threadIdx.x;
    const int EV = En / 4;
    if (idx >= NTOK * EV) return;
    int bs = idx / EV, e4 = idx % EV;
    int s = bs & (Sn - 1);
    int t = tokens[bs];
    float4 a = ((const float4*)tok)[(size_t)t * EV + e4];
    float4 p = ((const float4*)pos)[(size_t)s * EV + e4];
    float4 r;
    r.x = a.x + p.x; r.y = a.y + p.y; r.z = a.z + p.z; r.w = a.w + p.w;
    ((float4*)x)[idx] = r;
    bf16 h0, l0, h1, l1, h2, l2, h3, l3;
    split2(r.x, h0, l0); split2(r.y, h1, l1);
    split2(r.z, h2, l2); split2(r.w, h3, l3);
    ((uint2*)xh)[idx] = make_uint2(pack_bf(h0, h1), pack_bf(h2, h3));
    ((uint2*)xl)[idx] = make_uint2(pack_bf(l0, l1), pack_bf(l2, l3));
}

// ---------------- rmsnorm -> hi/lo bf16 ----------------
__global__ void add_rmsnorm_kernel(const float* __restrict__ x, const float* __restrict__ add,
                                   const float* __restrict__ scale,
                                   bf16* __restrict__ oh, bf16* __restrict__ ol)
{
    int row = blockIdx.x, tid = threadIdx.x;
    const float* xr = x + (size_t)row * En;
    const float* ar = add ? add + (size_t)row * En : nullptr;
    float v[4]; float ss = 0.f;
    #pragma unroll
    for (int j = 0; j < 4; j++) {
        int e = tid + j * 256;
        float t = xr[e];
        if (ar) t += ar[e];
        v[j] = t;
        ss += t * t;
    }
    ss = blockReduceSum(ss);
    float r = rsqrtf(ss * (1.f / En) + 1e-6f);
    #pragma unroll
    for (int j = 0; j < 4; j++) {
        int e = tid + j * 256;
        float t = v[j] * r * scale[e];
        bf16 h, l;
        split2(t, h, l);
        oh[(size_t)row * En + e] = h;
        ol[(size_t)row * En + e] = l;
    }
}

// ---------------- log_softmax ----------------
__global__ void log_softmax_kernel(float* __restrict__ a) {
    float* row = a + (size_t)blockIdx.x * Vn;
    int tid = threadIdx.x;
    float m = -3.402823466e38f;
    for (int i = tid; i < Vn; i += 256) m = fmaxf(m, row[i]);
    m = blockReduceMax(m);
    float s = 0.f;
    for (int i = tid; i < Vn; i += 256) s += __expf(row[i] - m);
    s = blockReduceSum(s);
    float lse = m + logf(s);
    for (int i = tid; i < Vn; i += 256) row[i] -= lse;
}

// ---------------- launch ----------------
extern "C" void kernel_launch(void* const* d_in, const int* in_sizes, int n_in,
                              void* d_out, int out_size) {
    const int*   tokens      = (const int*)  d_in[0];
    const float* tok_embed   = (const float*)d_in[1];
    const float* pos_embed   = (const float*)d_in[2];
    const float* Qw          = (const float*)d_in[3];
    const float* Kw          = (const float*)d_in[4];
    const float* Vw          = (const float*)d_in[5];
    const float* Ow          = (const float*)d_in[6];
    const float* rs2         = (const float*)d_in[7];
    const float* w1          = (const float*)d_in[8];
    const float* b1          = (const float*)d_in[9];
    const float* w2          = (const float*)d_in[10];
    const float* b2          = (const float*)d_in[11];
    const float* final_scale = (const float*)d_in[12];
    const float* w_out       = (const float*)d_in[13];
    const float* b_out       = (const float*)d_in[14];
    float* out = (float*)d_out;

    float *xb, *projb, *attb;
    bf16 *whi, *wlo, *ptb, *xh, *xl, *qh, *ql, *kh, *kl, *vt, *mh, *ml, *rh, *rl, *hh, *hl;
    cudaGetSymbolAddress((void**)&xb,    g_x);
    cudaGetSymbolAddress((void**)&projb, g_proj);
    cudaGetSymbolAddress((void**)&attb,  g_att);
    cudaGetSymbolAddress((void**)&ptb,   g_pt);
    cudaGetSymbolAddress((void**)&whi,   g_whi);
    cudaGetSymbolAddress((void**)&wlo,   g_wlo);
    cudaGetSymbolAddress((void**)&xh,    g_xh);
    cudaGetSymbolAddress((void**)&xl,    g_xl);
    cudaGetSymbolAddress((void**)&qh,    g_qh);
    cudaGetSymbolAddress((void**)&ql,    g_ql);
    cudaGetSymbolAddress((void**)&kh,    g_kh);
    cudaGetSymbolAddress((void**)&kl,    g_kl);
    cudaGetSymbolAddress((void**)&vt,    g_vt);
    cudaGetSymbolAddress((void**)&mh,    g_mh);
    cudaGetSymbolAddress((void**)&ml,    g_ml);
    cudaGetSymbolAddress((void**)&rh,    g_rh);
    cudaGetSymbolAddress((void**)&rl,    g_rl);
    cudaGetSymbolAddress((void**)&hh,    g_hh);
    cudaGetSymbolAddress((void**)&hl,    g_hl);

    cudaFuncSetAttribute(gemm_mma,    cudaFuncAttributeMaxDynamicSharedMemorySize, GM_SMEM);
    cudaFuncSetAttribute(scoresT_mma, cudaFuncAttributeMaxDynamicSharedMemorySize, SC_SMEM);
    cudaFuncSetAttribute(av_mma,      cudaFuncAttributeMaxDynamicSharedMemorySize, AV_SMEM);

    // ---- weight conversion: transpose + bf16 split ----
    dim3 cb(32, 8);
    for (int l = 0; l < Lnum; l++) {
        convert_w<<<dim3(32, 16), cb>>>(Qw + (size_t)l * M1, whi + (size_t)l * M1,
                                        wlo + (size_t)l * M1, En, HIDn);
        convert_w<<<dim3(32, 16), cb>>>(Kw + (size_t)l * M1, whi + 4 * (size_t)M1 + (size_t)l * M1,
                                        wlo + 4 * (size_t)M1 + (size_t)l * M1, En, HIDn);
        convert_w<<<dim3(32, 16), cb>>>(Vw + (size_t)l * M1, whi + 8 * (size_t)M1 + (size_t)l * M1,
                                        wlo + 8 * (size_t)M1 + (size_t)l * M1, En, HIDn);
        convert_w<<<dim3(32, 16), cb>>>(Ow + (size_t)l * M1, whi + 12 * (size_t)M1 + (size_t)l * M1,
                                        wlo + 12 * (size_t)M1 + (size_t)l * M1, HIDn, En);
        convert_w<<<dim3(128, 16), cb>>>(w1 + (size_t)l * 4 * M1,
                                         whi + 16 * (size_t)M1 + (size_t)l * 4 * M1,
                                         wlo + 16 * (size_t)M1 + (size_t)l * 4 * M1, En, FFn);
        convert_w<<<dim3(32, 64), cb>>>(w2 + (size_t)l * 4 * M1,
                                        whi + 32 * (size_t)M1 + (size_t)l * 4 * M1,
                                        wlo + 32 * (size_t)M1 + (size_t)l * 4 * M1, FFn, En);
    }
    convert_w<<<dim3(Vn / 32, 16), cb>>>(w_out, whi + 48 * (size_t)M1, wlo + 48 * (size_t)M1, En, Vn);

    embed_kernel<<<(NTOK * (En / 4) + 255) / 256, 256>>>(tokens, tok_embed, pos_embed, xb, xh, xl);

    for (int l = 0; l < Lnum; l++) {
        const bf16 *Qh = whi + (size_t)l * M1,                   *Ql2 = wlo + (size_t)l * M1;
        const bf16 *Kh = whi + 4 * (size_t)M1 + (size_t)l * M1,  *Kl2 = wlo + 4 * (size_t)M1 + (size_t)l * M1;
        const bf16 *Vh = whi + 8 * (size_t)M1 + (size_t)l * M1,  *Vl2 = wlo + 8 * (size_t)M1 + (size_t)l * M1;
        const bf16 *Oh = whi + 12 * (size_t)M1 + (size_t)l * M1, *Ol2 = wlo + 12 * (size_t)M1 + (size_t)l * M1;
        const bf16 *W1h = whi + 16 * (size_t)M1 + (size_t)l * 4 * M1,
                   *W1l = wlo + 16 * (size_t)M1 + (size_t)l * 4 * M1;
        const bf16 *W2h = whi + 32 * (size_t)M1 + (size_t)l * 4 * M1,
                   *W2l = wlo + 32 * (size_t)M1 + (size_t)l * 4 * M1;
        const float* r2l = rs2 + (size_t)l * En;
        const float* b1l = b1 + (size_t)l * FFn;
        const float* b2l = b2 + (size_t)l * En;

        dim3 g1024(HIDn / 128, NTOK / 128);
        gemm_mma<<<g1024, 256, GM_SMEM>>>(xh, xl, Qh, Ql2, nullptr, nullptr,
                                          nullptr, qh, ql, NTOK, HIDn, En, 0, 3);
        gemm_mma<<<g1024, 256, GM_SMEM>>>(xh, xl, Kh, Kl2, nullptr, nullptr,
                                          nullptr, kh, kl, NTOK, HIDn, En, 0, 3);
        gemm_mma<<<g1024, 256, GM_SMEM>>>(xh, xl, Vh, Vl2, nullptr, nullptr,
                                          nullptr, vt, nullptr, NTOK, HIDn, En, 0, 4);

        scoresT_mma<<<dim3(Sn / 128, Sn / 128, Bn * NHn), 256, SC_SMEM>>>(kh, kl, qh, ql, attb);
        col_softmax<<<dim3(Sn / 128, Bn * NHn), 128>>>(attb, ptb);
        av_mma<<<dim3(Sn / 128, Bn * NHn), 256, AV_SMEM>>>(ptb, vt, mh, ml);

        gemm_mma<<<g1024, 256, GM_SMEM>>>(mh, ml, Oh, Ol2, nullptr, nullptr,
                                          projb, nullptr, nullptr, NTOK, En, HIDn, 0, 0);
        add_rmsnorm_kernel<<<NTOK, 256>>>(xb, projb, r2l, rh, rl);

        gemm_mma<<<dim3(FFn / 128, NTOK / 128), 256, GM_SMEM>>>(rh, rl, W1h, W1l, b1l, nullptr,
                                                                nullptr, hh, hl, NTOK, FFn, En, 1 | 2, 2);
        gemm_mma<<<g1024, 256, GM_SMEM>>>(hh, hl, W2h, W2l, b2l, projb,
                                          xb, xh, xl, NTOK, En, FFn, 1 | 4, 1);
    }

    add_rmsnorm_kernel<<<NTOK, 256>>>(xb, nullptr, final_scale, xh, xl);

    gemm_mma<<<dim3(Vn / 128, NTOK / 128), 256, GM_SMEM>>>(xh, xl, whi + 48 * (size_t)M1,
                                                           wlo + 48 * (size_t)M1, b_out, nullptr,
                                                           out, nullptr, nullptr, NTOK, Vn, En, 1, 0);
    log_softmax_kernel<<<NTOK, 256>>>(out);
}